// round 1
// baseline (speedup 1.0000x reference)
#include <cuda_runtime.h>
#include <cstdint>

#define NB 4
#define NS 4096
#define ND 64
#define SCALE 0.125f
#define PADK 68
#define PADP 65
#define SMEM_BYTES ((2 * 64 * PADK + 64 * 64) * 4)

// Scratch (allocation-free rule: __device__ globals)
__device__ float g_kn[(size_t)NB * NS * ND];   // normalized keys, 4 MB
__device__ float g_shift[NB * NS];             // per-row shift m_i = |q_i| * d^-0.5
__device__ float g_rowsum[NB * NS];            // unnormalized softmax row sums

// ---------------------------------------------------------------------------
// Kernel 1: row norms -> normalized K + shift. One warp per row.
// ---------------------------------------------------------------------------
__global__ void prep_kernel(const float* __restrict__ qk) {
    int row  = blockIdx.x * 8 + (threadIdx.x >> 5);
    int lane = threadIdx.x & 31;
    const float* src = qk + (size_t)row * ND;
    float2 val = *(const float2*)(src + lane * 2);
    float ss = val.x * val.x + val.y * val.y;
    #pragma unroll
    for (int o = 16; o >= 1; o >>= 1) ss += __shfl_xor_sync(0xffffffffu, ss, o);
    float nrm = fmaxf(sqrtf(ss), 1e-12f);
    float inv = 1.0f / nrm;
    float2* dst = (float2*)(g_kn + (size_t)row * ND);
    dst[lane] = make_float2(val.x * inv, val.y * inv);
    if (lane == 0) g_shift[row] = nrm * SCALE;
}

// ---------------------------------------------------------------------------
// Kernel 2: fused QK^T -> exp(shifted) -> store p -> p@V accumulate.
// One CTA per (64-row tile, batch). Iterates col tiles ct <= rt (causal),
// then zero-fills upper-triangle tiles. Writes UNNORMALIZED p / out.
// ---------------------------------------------------------------------------
__global__ __launch_bounds__(256) void attn_main(
    const float* __restrict__ qk, const float* __restrict__ v,
    float* __restrict__ out, float* __restrict__ attn)
{
    extern __shared__ float sm[];
    float* Qts = sm;                  // [k][i], stride PADK (k-major)
    float* KPs = sm + 64 * PADK;      // K phase: [k][j] stride PADK; P phase: [j][i] stride PADP
    float* Vs  = sm + 2 * 64 * PADK;  // [j][e], stride 64
    __shared__ float shift_s[64];
    __shared__ float rowsum_s[64];

    const int tid = threadIdx.x;
    const int tx = tid & 15, ty = tid >> 4;
    const int rt = blockIdx.x, b = blockIdx.y;
    const size_t bS = (size_t)b * NS;

    if (tid < 64) {
        shift_s[tid]  = g_shift[bS + rt * 64 + tid];
        rowsum_s[tid] = 0.0f;
    }

    // Load Q tile transposed (raw qk rows)
    {
        const float* Qg = qk + (bS + rt * 64) * ND;
        int r = tid >> 4;
        int c = (tid & 15) * 4;
        #pragma unroll
        for (int it = 0; it < 4; ++it) {
            float4 q4 = *(const float4*)(Qg + (size_t)(it * 16 + r) * ND + c);
            Qts[(c + 0) * PADK + it * 16 + r] = q4.x;
            Qts[(c + 1) * PADK + it * 16 + r] = q4.y;
            Qts[(c + 2) * PADK + it * 16 + r] = q4.z;
            Qts[(c + 3) * PADK + it * 16 + r] = q4.w;
        }
    }

    float out_acc[4][4] = {};
    float* attn_b = attn + (size_t)b * NS * NS;

    for (int ct = 0; ct <= rt; ++ct) {
        __syncthreads();  // Q ready (iter 0) / prev AV done before smem overwrite
        {
            const float* Kg = g_kn + (bS + ct * 64) * ND;
            const float* Vg = v + (bS + ct * 64) * ND;
            int r = tid >> 4;
            int c = (tid & 15) * 4;
            #pragma unroll
            for (int it = 0; it < 4; ++it) {
                float4 k4 = *(const float4*)(Kg + (size_t)(it * 16 + r) * ND + c);
                KPs[(c + 0) * PADK + it * 16 + r] = k4.x;
                KPs[(c + 1) * PADK + it * 16 + r] = k4.y;
                KPs[(c + 2) * PADK + it * 16 + r] = k4.z;
                KPs[(c + 3) * PADK + it * 16 + r] = k4.w;
                float4 v4 = *(const float4*)(Vg + (size_t)(it * 16 + r) * ND + c);
                *(float4*)(Vs + (it * 16 + r) * 64 + c) = v4;
            }
        }
        __syncthreads();

        // --- dot GEMM: acc[ii][jj] = sum_k Q[i][k] * Kn[j][k] ---
        float acc[4][4] = {};
        #pragma unroll 8
        for (int k = 0; k < 64; ++k) {
            float4 a4 = *(const float4*)(Qts + k * PADK + 4 * ty);
            float4 b4 = *(const float4*)(KPs + k * PADK + 4 * tx);
            float a[4]  = {a4.x, a4.y, a4.z, a4.w};
            float bb[4] = {b4.x, b4.y, b4.z, b4.w};
            #pragma unroll
            for (int ii = 0; ii < 4; ++ii)
                #pragma unroll
                for (int jj = 0; jj < 4; ++jj)
                    acc[ii][jj] += a[ii] * bb[jj];
        }

        // --- shifted exp, row-sum reduce, store p to gmem ---
        #pragma unroll
        for (int ii = 0; ii < 4; ++ii) {
            int gi = rt * 64 + 4 * ty + ii;
            float sh = shift_s[4 * ty + ii];
            #pragma unroll
            for (int jj = 0; jj < 4; ++jj) {
                int gj = ct * 64 + 4 * tx + jj;
                // diag (-50000) and causal mask are exactly 0 after fp32 softmax
                acc[ii][jj] = (gj < gi) ? __expf(acc[ii][jj] * SCALE - sh) : 0.0f;
            }
            float s = acc[ii][0] + acc[ii][1] + acc[ii][2] + acc[ii][3];
            #pragma unroll
            for (int o = 8; o >= 1; o >>= 1) s += __shfl_xor_sync(0xffffffffu, s, o);
            if (tx == 0) rowsum_s[4 * ty + ii] += s;
            *(float4*)(attn_b + (size_t)gi * NS + ct * 64 + 4 * tx) =
                make_float4(acc[ii][0], acc[ii][1], acc[ii][2], acc[ii][3]);
        }
        __syncthreads();  // done reading K from KPs

        // store P transposed [j][i] for the AV GEMM
        #pragma unroll
        for (int jj = 0; jj < 4; ++jj)
            #pragma unroll
            for (int ii = 0; ii < 4; ++ii)
                KPs[(4 * tx + jj) * PADP + 4 * ty + ii] = acc[ii][jj];
        __syncthreads();

        // --- AV GEMM: out_acc[ii][ee] += sum_j p[i][j] * v[j][e] ---
        #pragma unroll 8
        for (int j = 0; j < 64; ++j) {
            float a0 = KPs[j * PADP + 4 * ty + 0];
            float a1 = KPs[j * PADP + 4 * ty + 1];
            float a2 = KPs[j * PADP + 4 * ty + 2];
            float a3 = KPs[j * PADP + 4 * ty + 3];
            float4 b4 = *(const float4*)(Vs + j * 64 + 4 * tx);
            float a[4]  = {a0, a1, a2, a3};
            float bb[4] = {b4.x, b4.y, b4.z, b4.w};
            #pragma unroll
            for (int ii = 0; ii < 4; ++ii)
                #pragma unroll
                for (int ee = 0; ee < 4; ++ee)
                    out_acc[ii][ee] += a[ii] * bb[ee];
        }
    }

    // Zero-fill upper-triangle tiles (attn is exactly 0 there)
    {
        int r = tid >> 4;
        int c = (tid & 15) * 4;
        float4 z = make_float4(0.f, 0.f, 0.f, 0.f);
        for (int ct = rt + 1; ct < 64; ++ct) {
            #pragma unroll
            for (int it = 0; it < 4; ++it)
                *(float4*)(attn_b + (size_t)(rt * 64 + it * 16 + r) * NS + ct * 64 + c) = z;
        }
    }

    __syncthreads();
    if (tid < 64) g_rowsum[bS + rt * 64 + tid] = rowsum_s[tid];
    #pragma unroll
    for (int ii = 0; ii < 4; ++ii) {
        int gi = rt * 64 + 4 * ty + ii;
        *(float4*)(out + (bS + gi) * ND + 4 * tx) =
            make_float4(out_acc[ii][0], out_acc[ii][1], out_acc[ii][2], out_acc[ii][3]);
    }
}

// ---------------------------------------------------------------------------
// Kernel 3: normalize attn row (lower triangle only) and out by 1/rowsum.
// Row 0 special case: softmax over single -50000 entry -> attn=e0, out=v0.
// ---------------------------------------------------------------------------
__global__ void normalize_kernel(float* __restrict__ out, float* __restrict__ attn,
                                 const float* __restrict__ v) {
    const int i = blockIdx.x;
    const int b = blockIdx.y;
    const int tid = threadIdx.x;
    const size_t row = (size_t)b * NS + i;
    float* arow = attn + (size_t)b * NS * NS + (size_t)i * NS;
    float* orow = out + row * ND;
    if (i == 0) {
        if (tid == 0) arow[0] = 1.0f;
        if (tid < 16)
            *(float4*)(orow + tid * 4) = *(const float4*)(v + row * ND + tid * 4);
        return;
    }
    const float inv = 1.0f / g_rowsum[row];
    const int n4 = (i >> 2) + 1;  // float4 chunks covering cols 0..i (trailing zeros stay 0)
    for (int c4 = tid; c4 < n4; c4 += blockDim.x) {
        float4 a = *(float4*)(arow + c4 * 4);
        a.x *= inv; a.y *= inv; a.z *= inv; a.w *= inv;
        *(float4*)(arow + c4 * 4) = a;
    }
    if (tid < 16) {
        float4 o = *(float4*)(orow + tid * 4);
        o.x *= inv; o.y *= inv; o.z *= inv; o.w *= inv;
        *(float4*)(orow + tid * 4) = o;
    }
}

// ---------------------------------------------------------------------------
extern "C" void kernel_launch(void* const* d_in, const int* in_sizes, int n_in,
                              void* d_out, int out_size) {
    const float* qk = (const float*)d_in[0];
    const float* v  = (const float*)d_in[1];
    float* out  = (float*)d_out;
    float* attn = out + (size_t)NB * NS * ND;

    cudaFuncSetAttribute(attn_main, cudaFuncAttributeMaxDynamicSharedMemorySize, SMEM_BYTES);
    prep_kernel<<<NB * NS / 8, 256>>>(qk);
    attn_main<<<dim3(64, NB), 256, SMEM_BYTES>>>(qk, v, out, attn);
    normalize_kernel<<<dim3(NS, NB), 256>>>(out, attn, v);
}

// round 3
// speedup vs baseline: 2.0061x; 2.0061x over previous
#include <cuda_runtime.h>
#include <cuda_bf16.h>
#include <cstdint>

#define NB 4
#define NS 4096
#define ND 64
#define SCALE 0.125f
#define STR 72u   // bf16 elements per smem row (144 B, 16B-aligned rows, conflict-free LDSM)

// dynamic smem byte offsets
#define O_QH 0u
#define O_QL 9216u
#define O_KH 18432u     // [2 bufs][64][STR]
#define O_KL 36864u
#define O_VH 55296u     // [2 bufs][64][STR], stored [j][e]
#define O_VL 73728u
#define O_PH 92160u     // [64][STR]
#define O_PL 101376u
#define SMEM_SZ 110592u

__device__ float g_kn[(size_t)NB * NS * ND];   // normalized keys
__device__ float g_shift[NB * NS];             // m_i = |q_i| * d^-0.5
__device__ float g_rowsum[NB * NS];            // unnormalized softmax row sums

// ------------------------------------------------------------- PTX helpers
__device__ __forceinline__ uint32_t smem_u32(const void* p) {
    uint32_t a;
    asm("{ .reg .u64 t; cvta.to.shared.u64 t, %1; cvt.u32.u64 %0, t; }" : "=r"(a) : "l"(p));
    return a;
}
__device__ __forceinline__ void ldsm4(uint32_t* d, uint32_t a) {
    asm volatile("ldmatrix.sync.aligned.m8n8.x4.shared.b16 {%0,%1,%2,%3}, [%4];"
                 : "=r"(d[0]), "=r"(d[1]), "=r"(d[2]), "=r"(d[3]) : "r"(a));
}
__device__ __forceinline__ void ldsm2(uint32_t* d, uint32_t a) {
    asm volatile("ldmatrix.sync.aligned.m8n8.x2.shared.b16 {%0,%1}, [%2];"
                 : "=r"(d[0]), "=r"(d[1]) : "r"(a));
}
__device__ __forceinline__ void ldsm2t(uint32_t* d, uint32_t a) {
    asm volatile("ldmatrix.sync.aligned.m8n8.x2.trans.shared.b16 {%0,%1}, [%2];"
                 : "=r"(d[0]), "=r"(d[1]) : "r"(a));
}
__device__ __forceinline__ void mma_bf16(float* c, const uint32_t* a, const uint32_t* b) {
    asm volatile("mma.sync.aligned.m16n8k16.row.col.f32.bf16.bf16.f32 "
                 "{%0,%1,%2,%3}, {%4,%5,%6,%7}, {%8,%9}, {%0,%1,%2,%3};"
                 : "+f"(c[0]), "+f"(c[1]), "+f"(c[2]), "+f"(c[3])
                 : "r"(a[0]), "r"(a[1]), "r"(a[2]), "r"(a[3]), "r"(b[0]), "r"(b[1]));
}
__device__ __forceinline__ uint32_t bfpack(__nv_bfloat16 a, __nv_bfloat16 b) {
    __nv_bfloat162 t = __halves2bfloat162(a, b);
    return *reinterpret_cast<uint32_t*>(&t);
}
__device__ __forceinline__ void split2(float a, float b, uint32_t& hi, uint32_t& lo) {
    __nv_bfloat16 ah = __float2bfloat16(a), bh = __float2bfloat16(b);
    __nv_bfloat16 al = __float2bfloat16(a - __bfloat162float(ah));
    __nv_bfloat16 bl = __float2bfloat16(b - __bfloat162float(bh));
    hi = bfpack(ah, bh);
    lo = bfpack(al, bl);
}

// ---------------------------------------------------------------------------
// Kernel 1: row norms -> normalized K + per-row shift. One warp per row.
// ---------------------------------------------------------------------------
__global__ void prep_kernel(const float* __restrict__ qk) {
    int row = blockIdx.x * 8 + (threadIdx.x >> 5);
    int lane = threadIdx.x & 31;
    const float* src = qk + (size_t)row * ND;
    float2 val = *(const float2*)(src + lane * 2);
    float ss = val.x * val.x + val.y * val.y;
    #pragma unroll
    for (int o = 16; o >= 1; o >>= 1) ss += __shfl_xor_sync(0xffffffffu, ss, o);
    float nrm = fmaxf(sqrtf(ss), 1e-12f);
    float inv = 1.0f / nrm;
    float2* dst = (float2*)(g_kn + (size_t)row * ND);
    dst[lane] = make_float2(val.x * inv, val.y * inv);
    if (lane == 0) g_shift[row] = nrm * SCALE;
}

// ---------------------------------------------------------------------------
// Kernel 2: HMMA fused QK^T -> exp -> attn store -> P@V. 64-row tile per CTA.
// ---------------------------------------------------------------------------
__global__ __launch_bounds__(256, 1)
void attn_main(const float* __restrict__ qk, const float* __restrict__ v,
               float* __restrict__ out, float* __restrict__ attn)
{
    extern __shared__ char smc[];
    const uint32_t sb = smem_u32(smc);
    const int tid = threadIdx.x, lane = tid & 31, wid = tid >> 5;
    const int wy = wid & 3, wx = wid >> 2;   // row group (16 rows), col half (32 cols)
    const int rt = 63 - blockIdx.x, b = blockIdx.y;  // big CTAs first
    const size_t bS = (size_t)b * NS;
    const int nt = rt + 1;

    __shared__ float shift_s[64];
    __shared__ float rspart[2][64];
    if (tid < 64) shift_s[tid] = g_shift[bS + rt * 64 + tid];

    // ---- Q tile load + split (pre-scaled by d^-0.5, exact pow2) ----
    {
        const float* Qg = qk + (bS + (size_t)rt * 64) * ND;
        int r = tid >> 2, cb = (tid & 3) * 16;
        float4 q[4];
        #pragma unroll
        for (int i = 0; i < 4; ++i)
            q[i] = *(const float4*)(Qg + (size_t)r * ND + cb + i * 4);
        uint32_t h[8], l[8];
        #pragma unroll
        for (int i = 0; i < 4; ++i) {
            split2(q[i].x * SCALE, q[i].y * SCALE, h[2 * i], l[2 * i]);
            split2(q[i].z * SCALE, q[i].w * SCALE, h[2 * i + 1], l[2 * i + 1]);
        }
        uint32_t off = (uint32_t)(r * STR + cb) * 2;
        *(uint4*)(smc + O_QH + off)      = make_uint4(h[0], h[1], h[2], h[3]);
        *(uint4*)(smc + O_QH + off + 16) = make_uint4(h[4], h[5], h[6], h[7]);
        *(uint4*)(smc + O_QL + off)      = make_uint4(l[0], l[1], l[2], l[3]);
        *(uint4*)(smc + O_QL + off + 16) = make_uint4(l[4], l[5], l[6], l[7]);
    }

    // ---- K/V tile prefetch (gmem->reg) and split-store (reg->smem) ----
    float4 kreg[4], vreg[4];
    const int r_ld = tid >> 2, cb_ld = (tid & 3) * 16;
    auto ldg_kv = [&](int ct) {
        const float* Kg = g_kn + (bS + (size_t)ct * 64 + r_ld) * ND + cb_ld;
        const float* Vg = v + (bS + (size_t)ct * 64 + r_ld) * ND + cb_ld;
        #pragma unroll
        for (int i = 0; i < 4; ++i) {
            kreg[i] = *(const float4*)(Kg + i * 4);
            vreg[i] = *(const float4*)(Vg + i * 4);
        }
    };
    auto sts_kv = [&](int buf) {
        uint32_t off = (uint32_t)(r_ld * STR + cb_ld) * 2;
        uint32_t h[8], l[8];
        #pragma unroll
        for (int i = 0; i < 4; ++i) {
            split2(kreg[i].x, kreg[i].y, h[2 * i], l[2 * i]);
            split2(kreg[i].z, kreg[i].w, h[2 * i + 1], l[2 * i + 1]);
        }
        *(uint4*)(smc + O_KH + buf * 9216u + off)      = make_uint4(h[0], h[1], h[2], h[3]);
        *(uint4*)(smc + O_KH + buf * 9216u + off + 16) = make_uint4(h[4], h[5], h[6], h[7]);
        *(uint4*)(smc + O_KL + buf * 9216u + off)      = make_uint4(l[0], l[1], l[2], l[3]);
        *(uint4*)(smc + O_KL + buf * 9216u + off + 16) = make_uint4(l[4], l[5], l[6], l[7]);
        #pragma unroll
        for (int i = 0; i < 4; ++i) {
            split2(vreg[i].x, vreg[i].y, h[2 * i], l[2 * i]);
            split2(vreg[i].z, vreg[i].w, h[2 * i + 1], l[2 * i + 1]);
        }
        *(uint4*)(smc + O_VH + buf * 9216u + off)      = make_uint4(h[0], h[1], h[2], h[3]);
        *(uint4*)(smc + O_VH + buf * 9216u + off + 16) = make_uint4(h[4], h[5], h[6], h[7]);
        *(uint4*)(smc + O_VL + buf * 9216u + off)      = make_uint4(l[0], l[1], l[2], l[3]);
        *(uint4*)(smc + O_VL + buf * 9216u + off + 16) = make_uint4(l[4], l[5], l[6], l[7]);
    };

    // ldmatrix address helpers
    auto A_addr = [&](uint32_t base, int row0, int k0) -> uint32_t {
        return sb + base + (uint32_t)((row0 + (lane & 15)) * STR + k0 + ((lane >> 4) << 3)) * 2;
    };
    auto B_addr = [&](uint32_t base, int j0, int k0) -> uint32_t {
        return sb + base + (uint32_t)((j0 + (lane & 7)) * STR + k0 + (((lane >> 3) & 1) << 3)) * 2;
    };
    auto Bt_addr = [&](uint32_t base, int j0, int e0) -> uint32_t {
        return sb + base + (uint32_t)((j0 + (lane & 15)) * STR + e0) * 2;
    };

    ldg_kv(0);
    sts_kv(0);
    __syncthreads();

    float oc[4][4] = {};
    float rs0 = 0.f, rs1 = 0.f;
    const int r0 = wy * 16 + (lane >> 2);
    const int gi0 = rt * 64 + r0, gi1 = gi0 + 8;
    float* attn_b = attn + (size_t)b * NS * NS;
    float* arow0 = attn_b + (size_t)gi0 * NS;
    float* arow1 = attn_b + (size_t)gi1 * NS;
    const float sh0 = shift_s[r0], sh1 = shift_s[r0 + 8];

    for (int ct = 0; ct < nt; ++ct) {
        const int buf = ct & 1;
        if (ct + 1 < nt) ldg_kv(ct + 1);

        // --- S = Qs @ Kn^T (split-fp32: hh + hl + lh) ---
        float sc[4][4] = {};
        const uint32_t khb = O_KH + buf * 9216u, klb = O_KL + buf * 9216u;
        #pragma unroll
        for (int k = 0; k < 4; ++k) {
            uint32_t ah[4], al[4];
            ldsm4(ah, A_addr(O_QH, wy * 16, k * 16));
            ldsm4(al, A_addr(O_QL, wy * 16, k * 16));
            #pragma unroll
            for (int nb = 0; nb < 4; ++nb) {
                uint32_t bh[2], bl[2];
                ldsm2(bh, B_addr(khb, wx * 32 + nb * 8, k * 16));
                ldsm2(bl, B_addr(klb, wx * 32 + nb * 8, k * 16));
                mma_bf16(sc[nb], ah, bh);
                mma_bf16(sc[nb], ah, bl);
                mma_bf16(sc[nb], al, bh);
            }
        }

        // --- exp + mask + attn store + P split to smem ---
        const int gjb = ct * 64 + wx * 32 + 2 * (lane & 3);
        #pragma unroll
        for (int nb = 0; nb < 4; ++nb) {
            int gj = gjb + nb * 8;
            float p00 = (gj < gi0)     ? __expf(sc[nb][0] - sh0) : 0.f;
            float p01 = (gj + 1 < gi0) ? __expf(sc[nb][1] - sh0) : 0.f;
            float p10 = (gj < gi1)     ? __expf(sc[nb][2] - sh1) : 0.f;
            float p11 = (gj + 1 < gi1) ? __expf(sc[nb][3] - sh1) : 0.f;
            rs0 += p00 + p01;
            rs1 += p10 + p11;
            *(float2*)(arow0 + gj) = make_float2(p00, p01);
            *(float2*)(arow1 + gj) = make_float2(p10, p11);
            uint32_t h0, l0, h1, l1;
            split2(p00, p01, h0, l0);
            split2(p10, p11, h1, l1);
            int cj = wx * 32 + nb * 8 + 2 * (lane & 3);
            uint32_t o0 = (uint32_t)(r0 * STR + cj) * 2;
            uint32_t o1 = (uint32_t)((r0 + 8) * STR + cj) * 2;
            *(uint32_t*)(smc + O_PH + o0) = h0;
            *(uint32_t*)(smc + O_PL + o0) = l0;
            *(uint32_t*)(smc + O_PH + o1) = h1;
            *(uint32_t*)(smc + O_PL + o1) = l1;
        }
        if (ct + 1 < nt) sts_kv(buf ^ 1);
        __syncthreads();  // P + next K/V visible

        // --- O += P @ V ---
        const uint32_t vhb = O_VH + buf * 9216u, vlb = O_VL + buf * 9216u;
        #pragma unroll
        for (int k = 0; k < 4; ++k) {
            uint32_t ah[4], al[4];
            ldsm4(ah, A_addr(O_PH, wy * 16, k * 16));
            ldsm4(al, A_addr(O_PL, wy * 16, k * 16));
            #pragma unroll
            for (int nb = 0; nb < 4; ++nb) {
                uint32_t bh[2], bl[2];
                ldsm2t(bh, Bt_addr(vhb, k * 16, wx * 32 + nb * 8));
                ldsm2t(bl, Bt_addr(vlb, k * 16, wx * 32 + nb * 8));
                mma_bf16(oc[nb], ah, bh);
                mma_bf16(oc[nb], ah, bl);
                mma_bf16(oc[nb], al, bh);
            }
        }
        __syncthreads();  // all AV reads of P done before next overwrite
    }

    // ---- combine rowsums across the two col-half warps (deterministic) ----
    rs0 += __shfl_xor_sync(0xffffffffu, rs0, 1);
    rs0 += __shfl_xor_sync(0xffffffffu, rs0, 2);
    rs1 += __shfl_xor_sync(0xffffffffu, rs1, 1);
    rs1 += __shfl_xor_sync(0xffffffffu, rs1, 2);
    if ((lane & 3) == 0) {
        rspart[wx][r0] = rs0;
        rspart[wx][r0 + 8] = rs1;
    }
    __syncthreads();
    const float rt0 = rspart[0][r0] + rspart[1][r0];
    const float rt1 = rspart[0][r0 + 8] + rspart[1][r0 + 8];
    if ((lane & 3) == 0 && wx == 0) {
        g_rowsum[bS + gi0] = rt0;
        g_rowsum[bS + gi1] = rt1;
    }

    // ---- out epilogue (normalized in-kernel) ----
    {
        float* o0 = out + (bS + gi0) * ND;
        float* o1 = out + (bS + gi1) * ND;
        if (gi0 == 0) {
            const float* vr = v + bS * ND;  // softmax over single -50000 diag -> out = v[0]
            #pragma unroll
            for (int nb = 0; nb < 4; ++nb) {
                int c = wx * 32 + nb * 8 + 2 * (lane & 3);
                *(float2*)(o0 + c) = *(const float2*)(vr + c);
            }
        } else {
            float inv0 = 1.0f / rt0;
            #pragma unroll
            for (int nb = 0; nb < 4; ++nb) {
                int c = wx * 32 + nb * 8 + 2 * (lane & 3);
                *(float2*)(o0 + c) = make_float2(oc[nb][0] * inv0, oc[nb][1] * inv0);
            }
        }
        float inv1 = 1.0f / rt1;
        #pragma unroll
        for (int nb = 0; nb < 4; ++nb) {
            int c = wx * 32 + nb * 8 + 2 * (lane & 3);
            *(float2*)(o1 + c) = make_float2(oc[nb][2] * inv1, oc[nb][3] * inv1);
        }
    }

    // ---- zero-fill upper-triangle columns ----
    {
        int cstart = nt * 64;
        int r = tid >> 2;
        float* rowp = attn_b + (size_t)(rt * 64 + r) * NS;
        float4 z = make_float4(0.f, 0.f, 0.f, 0.f);
        for (int c = cstart + (tid & 3) * 4; c < NS; c += 16)
            *(float4*)(rowp + c) = z;
    }
}

// ---------------------------------------------------------------------------
// Kernel 3: normalize attn rows (lower triangle only).
// ---------------------------------------------------------------------------
__global__ void normalize_attn(float* __restrict__ attn) {
    const int i = blockIdx.x, b = blockIdx.y, tid = threadIdx.x;
    float* arow = attn + (size_t)b * NS * NS + (size_t)i * NS;
    if (i == 0) { if (tid == 0) arow[0] = 1.0f; return; }
    const float inv = 1.0f / g_rowsum[(size_t)b * NS + i];
    const int n4 = (i >> 2) + 1;
    for (int c4 = tid; c4 < n4; c4 += blockDim.x) {
        float4 a = *(float4*)(arow + c4 * 4);
        a.x *= inv; a.y *= inv; a.z *= inv; a.w *= inv;
        *(float4*)(arow + c4 * 4) = a;
    }
}

// ---------------------------------------------------------------------------
extern "C" void kernel_launch(void* const* d_in, const int* in_sizes, int n_in,
                              void* d_out, int out_size) {
    const float* qk = (const float*)d_in[0];
    const float* v  = (const float*)d_in[1];
    float* out  = (float*)d_out;
    float* attn = out + (size_t)NB * NS * ND;

    cudaFuncSetAttribute(attn_main, cudaFuncAttributeMaxDynamicSharedMemorySize, SMEM_SZ);
    prep_kernel<<<NB * NS / 8, 256>>>(qk);
    attn_main<<<dim3(64, NB), 256, SMEM_SZ>>>(qk, v, out, attn);
    normalize_attn<<<dim3(NS, NB), 256>>>(attn);
}

// round 5
// speedup vs baseline: 2.6774x; 1.3346x over previous
#include <cuda_runtime.h>
#include <cuda_fp16.h>
#include <cstdint>

#define NB 4
#define NS 4096
#define ND 64
#define SCALE 0.125f
#define STR 72u          // fp16 elems per smem row (144 B -> LDSM conflict-free)
#define TBYTES 9216u     // one 64x72 fp16 tile

// dynamic smem byte offsets
#define O_QH 0u
#define O_QL 9216u
#define O_KH 18432u      // + buf*TBYTES (2 bufs)
#define O_KL 36864u      // + buf*TBYTES
#define O_VH 55296u      // + buf*TBYTES
#define O_VL 73728u      // + buf*TBYTES
#define SMEM_SZ 92160u

// pre-split fp16 operand arrays (uint32 = fp16x2), rows of 128 B
__device__ __align__(128) uint32_t g_qh[(size_t)NB * NS * 32];
__device__ __align__(128) uint32_t g_ql[(size_t)NB * NS * 32];
__device__ __align__(128) uint32_t g_kh[(size_t)NB * NS * 32];
__device__ __align__(128) uint32_t g_kl[(size_t)NB * NS * 32];
__device__ __align__(128) uint32_t g_vh[(size_t)NB * NS * 32];
__device__ __align__(128) uint32_t g_vl[(size_t)NB * NS * 32];
__device__ float g_shift[NB * NS];
__device__ float g_rowsum[NB * NS];

// ------------------------------------------------------------- PTX helpers
__device__ __forceinline__ uint32_t smem_u32(const void* p) {
    uint32_t a;
    asm("{ .reg .u64 t; cvta.to.shared.u64 t, %1; cvt.u32.u64 %0, t; }" : "=r"(a) : "l"(p));
    return a;
}
__device__ __forceinline__ uint64_t gaddr(const void* p) {
    uint64_t a;
    asm("cvta.to.global.u64 %0, %1;" : "=l"(a) : "l"(p));
    return a;
}
__device__ __forceinline__ void cp16(uint32_t dst, uint64_t src) {
    asm volatile("cp.async.cg.shared.global [%0], [%1], 16;" ::"r"(dst), "l"(src));
}
#define CP_COMMIT() asm volatile("cp.async.commit_group;" ::: "memory")
#define CP_WAIT0()  asm volatile("cp.async.wait_group 0;" ::: "memory")

__device__ __forceinline__ void ldsm4(uint32_t* d, uint32_t a) {
    asm volatile("ldmatrix.sync.aligned.m8n8.x4.shared.b16 {%0,%1,%2,%3}, [%4];"
                 : "=r"(d[0]), "=r"(d[1]), "=r"(d[2]), "=r"(d[3]) : "r"(a));
}
__device__ __forceinline__ void ldsm4t(uint32_t* d, uint32_t a) {
    asm volatile("ldmatrix.sync.aligned.m8n8.x4.trans.shared.b16 {%0,%1,%2,%3}, [%4];"
                 : "=r"(d[0]), "=r"(d[1]), "=r"(d[2]), "=r"(d[3]) : "r"(a));
}
__device__ __forceinline__ void mma_f16(float* c, const uint32_t* a, uint32_t b0, uint32_t b1) {
    asm volatile("mma.sync.aligned.m16n8k16.row.col.f32.f16.f16.f32 "
                 "{%0,%1,%2,%3}, {%4,%5,%6,%7}, {%8,%9}, {%0,%1,%2,%3};"
                 : "+f"(c[0]), "+f"(c[1]), "+f"(c[2]), "+f"(c[3])
                 : "r"(a[0]), "r"(a[1]), "r"(a[2]), "r"(a[3]), "r"(b0), "r"(b1));
}
__device__ __forceinline__ uint32_t h2u(__half2 h) { return *reinterpret_cast<uint32_t*>(&h); }
__device__ __forceinline__ void splith(float a, float b, uint32_t& hi, uint32_t& lo) {
    __half2 h = __floats2half2_rn(a, b);
    float2 f = __half22float2(h);
    __half2 l = __floats2half2_rn(a - f.x, b - f.y);
    hi = h2u(h);
    lo = h2u(l);
}

// ---------------------------------------------------------------------------
// Kernel 1: norms -> shift; pre-split Q*SCALE, Kn, V into fp16 hi/lo arrays.
// One warp per row.
// ---------------------------------------------------------------------------
__global__ void prep_kernel(const float* __restrict__ qk, const float* __restrict__ v) {
    int row = blockIdx.x * 8 + (threadIdx.x >> 5);
    int lane = threadIdx.x & 31;
    float2 q = *(const float2*)(qk + (size_t)row * ND + lane * 2);
    float ss = q.x * q.x + q.y * q.y;
    #pragma unroll
    for (int o = 16; o >= 1; o >>= 1) ss += __shfl_xor_sync(0xffffffffu, ss, o);
    float nrm = fmaxf(sqrtf(ss), 1e-12f);
    float inv = 1.0f / nrm;
    size_t w = (size_t)row * 32 + lane;
    uint32_t hi, lo;
    splith(q.x * SCALE, q.y * SCALE, hi, lo);
    g_qh[w] = hi; g_ql[w] = lo;
    splith(q.x * inv, q.y * inv, hi, lo);
    g_kh[w] = hi; g_kl[w] = lo;
    float2 vv = *(const float2*)(v + (size_t)row * ND + lane * 2);
    splith(vv.x, vv.y, hi, lo);
    g_vh[w] = hi; g_vl[w] = lo;
    if (lane == 0) g_shift[row] = nrm * SCALE;
}

// ---------------------------------------------------------------------------
// Kernel 2: fused QK^T -> exp -> attn store -> P@V (register P reuse).
// 4 warps, each 16 rows x 64 cols. Balanced static CTA->work schedule.
// ---------------------------------------------------------------------------
__global__ __launch_bounds__(128)
void attn_main(const float* __restrict__ v,
               float* __restrict__ out, float* __restrict__ attn)
{
    extern __shared__ char smc[];
    const uint32_t sb = smem_u32(smc);
    const int tid = threadIdx.x, lane = tid & 31, w = tid >> 5;

    // balanced schedule: paired SMs sum to 65 tile-iters
    int l = blockIdx.x, rt, b;
    if (l < 40)       { rt = 63 - (l >> 2); b = l & 3; }
    else if (l < 148) { int i = l - 40; rt = 53 - (i >> 2); b = i & 3; }
    else              { int i = l - 148; rt = i >> 2; b = i & 3; }
    const size_t bS = (size_t)b * NS;
    const int nt = rt + 1;

    __shared__ float shift_s[64];
    if (tid < 64) shift_s[tid] = g_shift[bS + rt * 64 + tid];

    const uint64_t gqh = gaddr(g_qh), gql = gaddr(g_ql);
    const uint64_t gkh = gaddr(g_kh), gkl = gaddr(g_kl);
    const uint64_t gvh = gaddr(g_vh), gvl = gaddr(g_vl);

    // Q tile cp.async (rows rt*64..+63)
    {
        size_t q0 = (bS + (size_t)rt * 64) * 128;  // byte offset of tile row 0
        #pragma unroll
        for (int c = 0; c < 4; ++c) {
            int idx = tid * 4 + c, r = idx >> 3, c8 = idx & 7;
            uint32_t so = (uint32_t)(r * 144 + c8 * 16);
            uint64_t go = q0 + (size_t)r * 128 + c8 * 16;
            cp16(sb + O_QH + so, gqh + go);
            cp16(sb + O_QL + so, gql + go);
        }
    }
    auto issue_kv = [&](int ct, int buf) {
        size_t t0 = (bS + (size_t)ct * 64) * 128;
        uint32_t kb = sb + O_KH + buf * TBYTES, lb = sb + O_KL + buf * TBYTES;
        uint32_t vb = sb + O_VH + buf * TBYTES, wb = sb + O_VL + buf * TBYTES;
        #pragma unroll
        for (int c = 0; c < 4; ++c) {
            int idx = tid * 4 + c, r = idx >> 3, c8 = idx & 7;
            uint32_t so = (uint32_t)(r * 144 + c8 * 16);
            uint64_t go = t0 + (size_t)r * 128 + c8 * 16;
            cp16(kb + so, gkh + go);
            cp16(lb + so, gkl + go);
            cp16(vb + so, gvh + go);
            cp16(wb + so, gvl + go);
        }
    };
    issue_kv(0, 0);
    CP_COMMIT();
    CP_WAIT0();
    __syncthreads();

    // ldmatrix byte-offset helpers (within a tile)
    const uint32_t A_off  = (uint32_t)(((lane & 15) * STR + ((lane >> 4) << 3)) * 2);
    const uint32_t B_off  = (uint32_t)(((((lane >> 4) << 3) + (lane & 7)) * STR + (((lane >> 3) & 1) << 3)) * 2);
    const uint32_t Vt_off = (uint32_t)(((lane & 15) * STR + ((lane >> 4) << 3)) * 2);

    const int g = lane >> 2, t = lane & 3;
    const int r0 = w * 16 + g;
    const int gi0 = rt * 64 + r0, gi1 = gi0 + 8;
    const float sh0 = shift_s[r0], sh1 = shift_s[r0 + 8];
    float* attn_b = attn + (size_t)b * NS * NS;
    float* arow0 = attn_b + (size_t)gi0 * NS;   // bare row pointers (col added via gj)
    float* arow1 = attn_b + (size_t)gi1 * NS;

    float oc[8][4] = {};
    float rs0 = 0.f, rs1 = 0.f;

    for (int ct = 0; ct < nt; ++ct) {
        const int buf = ct & 1;
        if (ct + 1 < nt) { issue_kv(ct + 1, buf ^ 1); CP_COMMIT(); }

        // --- S = Qs @ Kn^T (fp16 split: hh + hl + lh) ---
        float sc[8][4] = {};
        const uint32_t khb = sb + O_KH + buf * TBYTES, klb = sb + O_KL + buf * TBYTES;
        #pragma unroll
        for (int k = 0; k < 4; ++k) {
            uint32_t aq[4], al[4], bh[4], bl[4];
            uint32_t kcol = (uint32_t)(k * 16 * 2);
            ldsm4(aq, sb + O_QH + A_off + kcol + (uint32_t)(w * 16 * STR * 2));
            ldsm4(al, sb + O_QL + A_off + kcol + (uint32_t)(w * 16 * STR * 2));
            #pragma unroll
            for (int np = 0; np < 4; ++np) {
                uint32_t jo = (uint32_t)(np * 16 * STR * 2);
                ldsm4(bh, khb + B_off + jo + kcol);
                ldsm4(bl, klb + B_off + jo + kcol);
                mma_f16(sc[2 * np], aq, bh[0], bh[1]);
                mma_f16(sc[2 * np], aq, bl[0], bl[1]);
                mma_f16(sc[2 * np], al, bh[0], bh[1]);
                mma_f16(sc[2 * np + 1], aq, bh[2], bh[3]);
                mma_f16(sc[2 * np + 1], aq, bl[2], bl[3]);
                mma_f16(sc[2 * np + 1], al, bh[2], bh[3]);
            }
        }

        // --- exp + mask + attn store + register repack to fp16 A-frags ---
        uint32_t ah_[4][4], al_[4][4];
        const int gjb = ct * 64 + 2 * t;
        #pragma unroll
        for (int nb = 0; nb < 8; ++nb) {
            int gj = gjb + nb * 8;   // global col of this thread's pair
            float p00 = (gj < gi0)     ? __expf(sc[nb][0] - sh0) : 0.f;
            float p01 = (gj + 1 < gi0) ? __expf(sc[nb][1] - sh0) : 0.f;
            float p10 = (gj < gi1)     ? __expf(sc[nb][2] - sh1) : 0.f;
            float p11 = (gj + 1 < gi1) ? __expf(sc[nb][3] - sh1) : 0.f;
            rs0 += p00 + p01;
            rs1 += p10 + p11;
            *(float2*)(arow0 + gj) = make_float2(p00, p01);
            *(float2*)(arow1 + gj) = make_float2(p10, p11);
            uint32_t h0, l0, h1, l1;
            splith(p00, p01, h0, l0);
            splith(p10, p11, h1, l1);
            int kb = nb >> 1, o = (nb & 1) * 2;
            ah_[kb][o] = h0; ah_[kb][o + 1] = h1;
            al_[kb][o] = l0; al_[kb][o + 1] = l1;
        }

        // --- O += P @ V (A from registers, B = V via trans LDSM) ---
        const uint32_t vhb = sb + O_VH + buf * TBYTES, vlb = sb + O_VL + buf * TBYTES;
        #pragma unroll
        for (int kb = 0; kb < 4; ++kb) {
            uint32_t jo = (uint32_t)(kb * 16 * STR * 2);
            #pragma unroll
            for (int ep = 0; ep < 4; ++ep) {
                uint32_t vh[4], vl[4];
                uint32_t eo = (uint32_t)(ep * 16 * 2);
                ldsm4t(vh, vhb + Vt_off + jo + eo);
                ldsm4t(vl, vlb + Vt_off + jo + eo);
                mma_f16(oc[2 * ep], ah_[kb], vh[0], vh[1]);
                mma_f16(oc[2 * ep], ah_[kb], vl[0], vl[1]);
                mma_f16(oc[2 * ep], al_[kb], vh[0], vh[1]);
                mma_f16(oc[2 * ep + 1], ah_[kb], vh[2], vh[3]);
                mma_f16(oc[2 * ep + 1], ah_[kb], vl[2], vl[3]);
                mma_f16(oc[2 * ep + 1], al_[kb], vh[2], vh[3]);
            }
        }

        if (ct + 1 < nt) CP_WAIT0();
        __syncthreads();
    }

    // ---- rowsum reduce within the 4-thread column groups ----
    rs0 += __shfl_xor_sync(0xffffffffu, rs0, 1);
    rs0 += __shfl_xor_sync(0xffffffffu, rs0, 2);
    rs1 += __shfl_xor_sync(0xffffffffu, rs1, 1);
    rs1 += __shfl_xor_sync(0xffffffffu, rs1, 2);
    if (t == 0) {
        g_rowsum[bS + gi0] = rs0;
        g_rowsum[bS + gi1] = rs1;
    }

    // ---- out epilogue (normalized in-kernel) ----
    {
        float* o0 = out + (bS + gi0) * ND;
        float* o1 = out + (bS + gi1) * ND;
        if (gi0 == 0) {
            const float* vr = v + bS * ND;  // row 0: softmax over single -50000 diag
            #pragma unroll
            for (int nb = 0; nb < 8; ++nb) {
                int c = nb * 8 + 2 * t;
                *(float2*)(o0 + c) = *(const float2*)(vr + c);
            }
        } else {
            float i0 = 1.0f / rs0;
            #pragma unroll
            for (int nb = 0; nb < 8; ++nb) {
                int c = nb * 8 + 2 * t;
                *(float2*)(o0 + c) = make_float2(oc[nb][0] * i0, oc[nb][1] * i0);
            }
        }
        float i1 = 1.0f / rs1;
        #pragma unroll
        for (int nb = 0; nb < 8; ++nb) {
            int c = nb * 8 + 2 * t;
            *(float2*)(o1 + c) = make_float2(oc[nb][2] * i1, oc[nb][3] * i1);
        }
    }

    // ---- zero-fill upper-triangle columns ----
    {
        int cstart = nt * 64;
        int r = tid >> 1;
        float* rowp = attn_b + (size_t)(rt * 64 + r) * NS;
        float4 z = make_float4(0.f, 0.f, 0.f, 0.f);
        for (int c = cstart + (tid & 1) * 4; c < NS; c += 8)
            *(float4*)(rowp + c) = z;
    }
}

// ---------------------------------------------------------------------------
// Kernel 3: normalize attn rows (lower triangle only).
// ---------------------------------------------------------------------------
__global__ void normalize_attn(float* __restrict__ attn) {
    const int i = blockIdx.x, b = blockIdx.y, tid = threadIdx.x;
    float* arow = attn + (size_t)b * NS * NS + (size_t)i * NS;
    if (i == 0) { if (tid == 0) arow[0] = 1.0f; return; }
    const float inv = 1.0f / g_rowsum[(size_t)b * NS + i];
    const int n4 = (i >> 2) + 1;
    for (int c4 = tid; c4 < n4; c4 += blockDim.x) {
        float4 a = *(float4*)(arow + c4 * 4);
        a.x *= inv; a.y *= inv; a.z *= inv; a.w *= inv;
        *(float4*)(arow + c4 * 4) = a;
    }
}

// ---------------------------------------------------------------------------
extern "C" void kernel_launch(void* const* d_in, const int* in_sizes, int n_in,
                              void* d_out, int out_size) {
    const float* qk = (const float*)d_in[0];
    const float* v  = (const float*)d_in[1];
    float* out  = (float*)d_out;
    float* attn = out + (size_t)NB * NS * ND;

    cudaFuncSetAttribute(attn_main, cudaFuncAttributeMaxDynamicSharedMemorySize, SMEM_SZ);
    prep_kernel<<<NB * NS / 8, 256>>>(qk, v);
    attn_main<<<256, 128, SMEM_SZ>>>(v, out, attn);
    normalize_attn<<<dim3(NS, NB), 256>>>(attn);
}

// round 6
// speedup vs baseline: 3.1243x; 1.1669x over previous
#include <cuda_runtime.h>
#include <cuda_fp16.h>
#include <cstdint>

#define NB 4
#define NS 4096
#define ND 64
#define SCALE 0.125f
#define STR 72u          // fp16 elems per smem row (144 B -> LDSM conflict-free)
#define TBYTES 9216u     // one 64x72 fp16 tile

// dynamic smem byte offsets
#define O_QH 0u
#define O_QL 9216u
#define O_KH 18432u      // + buf*TBYTES (2 bufs)
#define O_KL 36864u      // + buf*TBYTES
#define O_VH 55296u      // + buf*TBYTES (single precision V)
#define SMEM_SZ 73728u

// pre-split fp16 operand arrays (uint32 = fp16x2), rows of 128 B
__device__ __align__(128) uint32_t g_qh[(size_t)NB * NS * 32];
__device__ __align__(128) uint32_t g_ql[(size_t)NB * NS * 32];
__device__ __align__(128) uint32_t g_kh[(size_t)NB * NS * 32];
__device__ __align__(128) uint32_t g_kl[(size_t)NB * NS * 32];
__device__ __align__(128) uint32_t g_vh[(size_t)NB * NS * 32];
__device__ float g_shift[NB * NS];
__device__ float g_rowsum[NB * NS];

// ------------------------------------------------------------- PTX helpers
__device__ __forceinline__ uint32_t smem_u32(const void* p) {
    uint32_t a;
    asm("{ .reg .u64 t; cvta.to.shared.u64 t, %1; cvt.u32.u64 %0, t; }" : "=r"(a) : "l"(p));
    return a;
}
__device__ __forceinline__ uint64_t gaddr(const void* p) {
    uint64_t a;
    asm("cvta.to.global.u64 %0, %1;" : "=l"(a) : "l"(p));
    return a;
}
__device__ __forceinline__ void cp16(uint32_t dst, uint64_t src) {
    asm volatile("cp.async.cg.shared.global [%0], [%1], 16;" ::"r"(dst), "l"(src));
}
#define CP_COMMIT() asm volatile("cp.async.commit_group;" ::: "memory")
#define CP_WAIT0()  asm volatile("cp.async.wait_group 0;" ::: "memory")

__device__ __forceinline__ void ldsm4(uint32_t* d, uint32_t a) {
    asm volatile("ldmatrix.sync.aligned.m8n8.x4.shared.b16 {%0,%1,%2,%3}, [%4];"
                 : "=r"(d[0]), "=r"(d[1]), "=r"(d[2]), "=r"(d[3]) : "r"(a));
}
__device__ __forceinline__ void ldsm4t(uint32_t* d, uint32_t a) {
    asm volatile("ldmatrix.sync.aligned.m8n8.x4.trans.shared.b16 {%0,%1,%2,%3}, [%4];"
                 : "=r"(d[0]), "=r"(d[1]), "=r"(d[2]), "=r"(d[3]) : "r"(a));
}
__device__ __forceinline__ void mma_f16(float* c, const uint32_t* a, uint32_t b0, uint32_t b1) {
    asm volatile("mma.sync.aligned.m16n8k16.row.col.f32.f16.f16.f32 "
                 "{%0,%1,%2,%3}, {%4,%5,%6,%7}, {%8,%9}, {%0,%1,%2,%3};"
                 : "+f"(c[0]), "+f"(c[1]), "+f"(c[2]), "+f"(c[3])
                 : "r"(a[0]), "r"(a[1]), "r"(a[2]), "r"(a[3]), "r"(b0), "r"(b1));
}
__device__ __forceinline__ uint32_t h2u(__half2 h) { return *reinterpret_cast<uint32_t*>(&h); }
__device__ __forceinline__ void splith(float a, float b, uint32_t& hi, uint32_t& lo) {
    __half2 h = __floats2half2_rn(a, b);
    float2 f = __half22float2(h);
    __half2 l = __floats2half2_rn(a - f.x, b - f.y);
    hi = h2u(h);
    lo = h2u(l);
}

// ---------------------------------------------------------------------------
// Kernel 1: norms -> shift; pre-split Q*SCALE, Kn (hi/lo) and V (fp16) arrays.
// One warp per row.
// ---------------------------------------------------------------------------
__global__ void prep_kernel(const float* __restrict__ qk, const float* __restrict__ v) {
    int row = blockIdx.x * 8 + (threadIdx.x >> 5);
    int lane = threadIdx.x & 31;
    float2 q = *(const float2*)(qk + (size_t)row * ND + lane * 2);
    float ss = q.x * q.x + q.y * q.y;
    #pragma unroll
    for (int o = 16; o >= 1; o >>= 1) ss += __shfl_xor_sync(0xffffffffu, ss, o);
    float nrm = fmaxf(sqrtf(ss), 1e-12f);
    float inv = 1.0f / nrm;
    size_t w = (size_t)row * 32 + lane;
    uint32_t hi, lo;
    splith(q.x * SCALE, q.y * SCALE, hi, lo);
    g_qh[w] = hi; g_ql[w] = lo;
    splith(q.x * inv, q.y * inv, hi, lo);
    g_kh[w] = hi; g_kl[w] = lo;
    float2 vv = *(const float2*)(v + (size_t)row * ND + lane * 2);
    g_vh[w] = h2u(__floats2half2_rn(vv.x, vv.y));
    if (lane == 0) g_shift[row] = nrm * SCALE;
}

// ---------------------------------------------------------------------------
// Kernel 2: fused QK^T (3-term split) -> exp -> attn store -> P@V (1-term).
// 4 warps, each 16 rows x 64 cols. Balanced static CTA->work schedule.
// ---------------------------------------------------------------------------
__global__ __launch_bounds__(128)
void attn_main(const float* __restrict__ v,
               float* __restrict__ out, float* __restrict__ attn)
{
    extern __shared__ char smc[];
    const uint32_t sb = smem_u32(smc);
    const int tid = threadIdx.x, lane = tid & 31, w = tid >> 5;

    // balanced schedule: paired SMs sum to 65 tile-iters
    int l = blockIdx.x, rt, b;
    if (l < 40)       { rt = 63 - (l >> 2); b = l & 3; }
    else if (l < 148) { int i = l - 40; rt = 53 - (i >> 2); b = i & 3; }
    else              { int i = l - 148; rt = i >> 2; b = i & 3; }
    const size_t bS = (size_t)b * NS;
    const int nt = rt + 1;

    __shared__ float shift_s[64];
    if (tid < 64) shift_s[tid] = g_shift[bS + rt * 64 + tid];

    const uint64_t gqh = gaddr(g_qh), gql = gaddr(g_ql);
    const uint64_t gkh = gaddr(g_kh), gkl = gaddr(g_kl);
    const uint64_t gvh = gaddr(g_vh);

    // Q tile cp.async (rows rt*64..+63)
    {
        size_t q0 = (bS + (size_t)rt * 64) * 128;  // byte offset of tile row 0
        #pragma unroll
        for (int c = 0; c < 4; ++c) {
            int idx = tid * 4 + c, r = idx >> 3, c8 = idx & 7;
            uint32_t so = (uint32_t)(r * 144 + c8 * 16);
            uint64_t go = q0 + (size_t)r * 128 + c8 * 16;
            cp16(sb + O_QH + so, gqh + go);
            cp16(sb + O_QL + so, gql + go);
        }
    }
    auto issue_kv = [&](int ct, int buf) {
        size_t t0 = (bS + (size_t)ct * 64) * 128;
        uint32_t kb = sb + O_KH + buf * TBYTES, lb = sb + O_KL + buf * TBYTES;
        uint32_t vb = sb + O_VH + buf * TBYTES;
        #pragma unroll
        for (int c = 0; c < 4; ++c) {
            int idx = tid * 4 + c, r = idx >> 3, c8 = idx & 7;
            uint32_t so = (uint32_t)(r * 144 + c8 * 16);
            uint64_t go = t0 + (size_t)r * 128 + c8 * 16;
            cp16(kb + so, gkh + go);
            cp16(lb + so, gkl + go);
            cp16(vb + so, gvh + go);
        }
    };
    issue_kv(0, 0);
    CP_COMMIT();
    CP_WAIT0();
    __syncthreads();

    // ldmatrix byte-offset helpers (within a tile)
    const uint32_t A_off  = (uint32_t)(((lane & 15) * STR + ((lane >> 4) << 3)) * 2);
    const uint32_t B_off  = (uint32_t)(((((lane >> 4) << 3) + (lane & 7)) * STR + (((lane >> 3) & 1) << 3)) * 2);
    const uint32_t Vt_off = (uint32_t)(((lane & 15) * STR + ((lane >> 4) << 3)) * 2);

    const int g = lane >> 2, t = lane & 3;
    const int r0 = w * 16 + g;
    const int gi0 = rt * 64 + r0, gi1 = gi0 + 8;
    const float sh0 = shift_s[r0], sh1 = shift_s[r0 + 8];
    float* attn_b = attn + (size_t)b * NS * NS;
    float* arow0 = attn_b + (size_t)gi0 * NS;   // bare row pointers (col added via gj)
    float* arow1 = attn_b + (size_t)gi1 * NS;

    float oc[8][4] = {};
    float rs0 = 0.f, rs1 = 0.f;

    for (int ct = 0; ct < nt; ++ct) {
        const int buf = ct & 1;
        if (ct + 1 < nt) { issue_kv(ct + 1, buf ^ 1); CP_COMMIT(); }

        // --- S = Qs @ Kn^T (fp16 split: hh + hl + lh) ---
        float sc[8][4] = {};
        const uint32_t khb = sb + O_KH + buf * TBYTES, klb = sb + O_KL + buf * TBYTES;
        #pragma unroll
        for (int k = 0; k < 4; ++k) {
            uint32_t aq[4], al[4], bh[4], bl[4];
            uint32_t kcol = (uint32_t)(k * 16 * 2);
            ldsm4(aq, sb + O_QH + A_off + kcol + (uint32_t)(w * 16 * STR * 2));
            ldsm4(al, sb + O_QL + A_off + kcol + (uint32_t)(w * 16 * STR * 2));
            #pragma unroll
            for (int np = 0; np < 4; ++np) {
                uint32_t jo = (uint32_t)(np * 16 * STR * 2);
                ldsm4(bh, khb + B_off + jo + kcol);
                ldsm4(bl, klb + B_off + jo + kcol);
                mma_f16(sc[2 * np], aq, bh[0], bh[1]);
                mma_f16(sc[2 * np], aq, bl[0], bl[1]);
                mma_f16(sc[2 * np], al, bh[0], bh[1]);
                mma_f16(sc[2 * np + 1], aq, bh[2], bh[3]);
                mma_f16(sc[2 * np + 1], aq, bl[2], bl[3]);
                mma_f16(sc[2 * np + 1], al, bh[2], bh[3]);
            }
        }

        // --- exp + mask + attn store + register repack to fp16 A-frags ---
        uint32_t ah_[4][4];
        const int gjb = ct * 64 + 2 * t;
        #pragma unroll
        for (int nb = 0; nb < 8; ++nb) {
            int gj = gjb + nb * 8;   // global col of this thread's pair
            float p00 = (gj < gi0)     ? __expf(sc[nb][0] - sh0) : 0.f;
            float p01 = (gj + 1 < gi0) ? __expf(sc[nb][1] - sh0) : 0.f;
            float p10 = (gj < gi1)     ? __expf(sc[nb][2] - sh1) : 0.f;
            float p11 = (gj + 1 < gi1) ? __expf(sc[nb][3] - sh1) : 0.f;
            rs0 += p00 + p01;
            rs1 += p10 + p11;
            *(float2*)(arow0 + gj) = make_float2(p00, p01);
            *(float2*)(arow1 + gj) = make_float2(p10, p11);
            int kb = nb >> 1, o = (nb & 1) * 2;
            ah_[kb][o]     = h2u(__floats2half2_rn(p00, p01));
            ah_[kb][o + 1] = h2u(__floats2half2_rn(p10, p11));
        }

        // --- O += P @ V (single fp16 term; A from registers, B via trans LDSM) ---
        const uint32_t vhb = sb + O_VH + buf * TBYTES;
        #pragma unroll
        for (int kb = 0; kb < 4; ++kb) {
            uint32_t jo = (uint32_t)(kb * 16 * STR * 2);
            #pragma unroll
            for (int ep = 0; ep < 4; ++ep) {
                uint32_t vh[4];
                ldsm4t(vh, vhb + Vt_off + jo + (uint32_t)(ep * 16 * 2));
                mma_f16(oc[2 * ep],     ah_[kb], vh[0], vh[1]);
                mma_f16(oc[2 * ep + 1], ah_[kb], vh[2], vh[3]);
            }
        }

        if (ct + 1 < nt) CP_WAIT0();
        __syncthreads();
    }

    // ---- rowsum reduce within the 4-thread column groups ----
    rs0 += __shfl_xor_sync(0xffffffffu, rs0, 1);
    rs0 += __shfl_xor_sync(0xffffffffu, rs0, 2);
    rs1 += __shfl_xor_sync(0xffffffffu, rs1, 1);
    rs1 += __shfl_xor_sync(0xffffffffu, rs1, 2);
    if (t == 0) {
        g_rowsum[bS + gi0] = rs0;
        g_rowsum[bS + gi1] = rs1;
    }

    // ---- out epilogue (normalized in-kernel) ----
    {
        float* o0 = out + (bS + gi0) * ND;
        float* o1 = out + (bS + gi1) * ND;
        if (gi0 == 0) {
            const float* vr = v + bS * ND;  // row 0: softmax over single -50000 diag
            #pragma unroll
            for (int nb = 0; nb < 8; ++nb) {
                int c = nb * 8 + 2 * t;
                *(float2*)(o0 + c) = *(const float2*)(vr + c);
            }
        } else {
            float i0 = 1.0f / rs0;
            #pragma unroll
            for (int nb = 0; nb < 8; ++nb) {
                int c = nb * 8 + 2 * t;
                *(float2*)(o0 + c) = make_float2(oc[nb][0] * i0, oc[nb][1] * i0);
            }
        }
        float i1 = 1.0f / rs1;
        #pragma unroll
        for (int nb = 0; nb < 8; ++nb) {
            int c = nb * 8 + 2 * t;
            *(float2*)(o1 + c) = make_float2(oc[nb][2] * i1, oc[nb][3] * i1);
        }
    }

    // ---- zero-fill upper-triangle columns ----
    {
        int cstart = nt * 64;
        int r = tid >> 1;
        float* rowp = attn_b + (size_t)(rt * 64 + r) * NS;
        float4 z = make_float4(0.f, 0.f, 0.f, 0.f);
        for (int c = cstart + (tid & 1) * 4; c < NS; c += 8)
            *(float4*)(rowp + c) = z;
    }
}

// ---------------------------------------------------------------------------
// Kernel 3: normalize attn rows (lower triangle only).
// ---------------------------------------------------------------------------
__global__ void normalize_attn(float* __restrict__ attn) {
    const int i = blockIdx.x, b = blockIdx.y, tid = threadIdx.x;
    float* arow = attn + (size_t)b * NS * NS + (size_t)i * NS;
    if (i == 0) { if (tid == 0) arow[0] = 1.0f; return; }
    const float inv = 1.0f / g_rowsum[(size_t)b * NS + i];
    const int n4 = (i >> 2) + 1;
    for (int c4 = tid; c4 < n4; c4 += blockDim.x) {
        float4 a = *(float4*)(arow + c4 * 4);
        a.x *= inv; a.y *= inv; a.z *= inv; a.w *= inv;
        *(float4*)(arow + c4 * 4) = a;
    }
}

// ---------------------------------------------------------------------------
extern "C" void kernel_launch(void* const* d_in, const int* in_sizes, int n_in,
                              void* d_out, int out_size) {
    const float* qk = (const float*)d_in[0];
    const float* v  = (const float*)d_in[1];
    float* out  = (float*)d_out;
    float* attn = out + (size_t)NB * NS * ND;

    cudaFuncSetAttribute(attn_main, cudaFuncAttributeMaxDynamicSharedMemorySize, SMEM_SZ);
    prep_kernel<<<NB * NS / 8, 256>>>(qk, v);
    attn_main<<<256, 128, SMEM_SZ>>>(v, out, attn);
    normalize_attn<<<dim3(NS, NB), 256>>>(attn);
}

// round 7
// speedup vs baseline: 3.3295x; 1.0657x over previous
#include <cuda_runtime.h>
#include <cuda_fp16.h>
#include <cstdint>

#define NB 4
#define NS 4096
#define ND 64
#define SCALE 0.125f
#define STR 72u          // fp16 elems per smem row (144 B -> LDSM conflict-free)
#define TBYTES 9216u     // one 64x72 fp16 tile

// dynamic smem byte offsets
#define O_QH 0u
#define O_KH 9216u       // + buf*TBYTES (2 bufs)
#define O_KL 27648u      // + buf*TBYTES
#define O_VH 46080u      // + buf*TBYTES
#define SMEM_SZ 64512u

// pre-split fp16 operand arrays (uint32 = fp16x2), rows of 128 B
__device__ __align__(128) uint32_t g_qh[(size_t)NB * NS * 32];  // fp16(q*SCALE)
__device__ __align__(128) uint32_t g_kh[(size_t)NB * NS * 32];  // fp16 hi of kn
__device__ __align__(128) uint32_t g_kl[(size_t)NB * NS * 32];  // fp16 lo of kn
__device__ __align__(128) uint32_t g_vh[(size_t)NB * NS * 32];  // fp16(v)
__device__ float g_shift[NB * NS];
__device__ float g_rowsum[NB * NS];

// ------------------------------------------------------------- PTX helpers
__device__ __forceinline__ uint32_t smem_u32(const void* p) {
    uint32_t a;
    asm("{ .reg .u64 t; cvta.to.shared.u64 t, %1; cvt.u32.u64 %0, t; }" : "=r"(a) : "l"(p));
    return a;
}
__device__ __forceinline__ uint64_t gaddr(const void* p) {
    uint64_t a;
    asm("cvta.to.global.u64 %0, %1;" : "=l"(a) : "l"(p));
    return a;
}
__device__ __forceinline__ void cp16(uint32_t dst, uint64_t src) {
    asm volatile("cp.async.cg.shared.global [%0], [%1], 16;" ::"r"(dst), "l"(src));
}
#define CP_COMMIT() asm volatile("cp.async.commit_group;" ::: "memory")
#define CP_WAIT0()  asm volatile("cp.async.wait_group 0;" ::: "memory")

__device__ __forceinline__ void ldsm4(uint32_t* d, uint32_t a) {
    asm volatile("ldmatrix.sync.aligned.m8n8.x4.shared.b16 {%0,%1,%2,%3}, [%4];"
                 : "=r"(d[0]), "=r"(d[1]), "=r"(d[2]), "=r"(d[3]) : "r"(a));
}
__device__ __forceinline__ void ldsm4t(uint32_t* d, uint32_t a) {
    asm volatile("ldmatrix.sync.aligned.m8n8.x4.trans.shared.b16 {%0,%1,%2,%3}, [%4];"
                 : "=r"(d[0]), "=r"(d[1]), "=r"(d[2]), "=r"(d[3]) : "r"(a));
}
__device__ __forceinline__ void mma_f16(float* c, const uint32_t* a, uint32_t b0, uint32_t b1) {
    asm volatile("mma.sync.aligned.m16n8k16.row.col.f32.f16.f16.f32 "
                 "{%0,%1,%2,%3}, {%4,%5,%6,%7}, {%8,%9}, {%0,%1,%2,%3};"
                 : "+f"(c[0]), "+f"(c[1]), "+f"(c[2]), "+f"(c[3])
                 : "r"(a[0]), "r"(a[1]), "r"(a[2]), "r"(a[3]), "r"(b0), "r"(b1));
}
__device__ __forceinline__ uint32_t h2u(__half2 h) { return *reinterpret_cast<uint32_t*>(&h); }
__device__ __forceinline__ void splith(float a, float b, uint32_t& hi, uint32_t& lo) {
    __half2 h = __floats2half2_rn(a, b);
    float2 f = __half22float2(h);
    __half2 l = __floats2half2_rn(a - f.x, b - f.y);
    hi = h2u(h);
    lo = h2u(l);
}

// ---------------------------------------------------------------------------
// Kernel 1: norms -> shift; fp16 Q*SCALE, split Kn (hi/lo), fp16 V.
// One warp per row.
// ---------------------------------------------------------------------------
__global__ void prep_kernel(const float* __restrict__ qk, const float* __restrict__ v) {
    int row = blockIdx.x * 8 + (threadIdx.x >> 5);
    int lane = threadIdx.x & 31;
    float2 q = *(const float2*)(qk + (size_t)row * ND + lane * 2);
    float ss = q.x * q.x + q.y * q.y;
    #pragma unroll
    for (int o = 16; o >= 1; o >>= 1) ss += __shfl_xor_sync(0xffffffffu, ss, o);
    float nrm = fmaxf(sqrtf(ss), 1e-12f);
    float inv = 1.0f / nrm;
    size_t w = (size_t)row * 32 + lane;
    g_qh[w] = h2u(__floats2half2_rn(q.x * SCALE, q.y * SCALE));
    uint32_t hi, lo;
    splith(q.x * inv, q.y * inv, hi, lo);
    g_kh[w] = hi; g_kl[w] = lo;
    float2 vv = *(const float2*)(v + (size_t)row * ND + lane * 2);
    g_vh[w] = h2u(__floats2half2_rn(vv.x, vv.y));
    if (lane == 0) g_shift[row] = nrm * SCALE;
}

// ---------------------------------------------------------------------------
// Kernel 2: fused QK^T (2-term: qh*kh + qh*kl) -> exp -> attn -> P@V (1-term).
// 4 warps, each 16 rows x 64 cols. Balanced static CTA->work schedule.
// ---------------------------------------------------------------------------
__global__ __launch_bounds__(128)
void attn_main(const float* __restrict__ v,
               float* __restrict__ out, float* __restrict__ attn)
{
    extern __shared__ char smc[];
    const uint32_t sb = smem_u32(smc);
    const int tid = threadIdx.x, lane = tid & 31, w = tid >> 5;

    // balanced schedule: paired SMs sum to 65 tile-iters
    int l = blockIdx.x, rt, b;
    if (l < 40)       { rt = 63 - (l >> 2); b = l & 3; }
    else if (l < 148) { int i = l - 40; rt = 53 - (i >> 2); b = i & 3; }
    else              { int i = l - 148; rt = i >> 2; b = i & 3; }
    const size_t bS = (size_t)b * NS;
    const int nt = rt + 1;

    __shared__ float shift_s[64];
    if (tid < 64) shift_s[tid] = g_shift[bS + rt * 64 + tid];

    const uint64_t gqh = gaddr(g_qh);
    const uint64_t gkh = gaddr(g_kh), gkl = gaddr(g_kl);
    const uint64_t gvh = gaddr(g_vh);

    // Q tile cp.async (rows rt*64..+63): 8192 B = 512 chunks, 4 per thread
    {
        size_t q0 = (bS + (size_t)rt * 64) * 128;  // byte offset of tile row 0
        #pragma unroll
        for (int c = 0; c < 4; ++c) {
            int idx = tid * 4 + c, r = idx >> 3, c8 = idx & 7;
            cp16(sb + O_QH + (uint32_t)(r * 144 + c8 * 16),
                 gqh + q0 + (size_t)r * 128 + c8 * 16);
        }
    }
    auto issue_kv = [&](int ct, int buf) {
        size_t t0 = (bS + (size_t)ct * 64) * 128;
        uint32_t kb = sb + O_KH + buf * TBYTES, lb = sb + O_KL + buf * TBYTES;
        uint32_t vb = sb + O_VH + buf * TBYTES;
        #pragma unroll
        for (int c = 0; c < 4; ++c) {
            int idx = tid * 4 + c, r = idx >> 3, c8 = idx & 7;
            uint32_t so = (uint32_t)(r * 144 + c8 * 16);
            uint64_t go = t0 + (size_t)r * 128 + c8 * 16;
            cp16(kb + so, gkh + go);
            cp16(lb + so, gkl + go);
            cp16(vb + so, gvh + go);
        }
    };
    issue_kv(0, 0);
    CP_COMMIT();
    CP_WAIT0();
    __syncthreads();

    // ldmatrix byte-offset helpers (within a tile)
    const uint32_t A_off  = (uint32_t)(((lane & 15) * STR + ((lane >> 4) << 3)) * 2);
    const uint32_t B_off  = (uint32_t)(((((lane >> 4) << 3) + (lane & 7)) * STR + (((lane >> 3) & 1) << 3)) * 2);
    const uint32_t Vt_off = (uint32_t)(((lane & 15) * STR + ((lane >> 4) << 3)) * 2);

    const int g = lane >> 2, t = lane & 3;
    const int r0 = w * 16 + g;
    const int gi0 = rt * 64 + r0, gi1 = gi0 + 8;
    const float sh0 = shift_s[r0], sh1 = shift_s[r0 + 8];
    float* attn_b = attn + (size_t)b * NS * NS;
    float* arow0 = attn_b + (size_t)gi0 * NS;   // bare row pointers (col added via gj)
    float* arow1 = attn_b + (size_t)gi1 * NS;

    float oc[8][4] = {};
    float rs0 = 0.f, rs1 = 0.f;

    for (int ct = 0; ct < nt; ++ct) {
        const int buf = ct & 1;
        if (ct + 1 < nt) { issue_kv(ct + 1, buf ^ 1); CP_COMMIT(); }

        // --- S = Qs @ Kn^T (2-term: aq*kh + aq*kl) ---
        float sc[8][4] = {};
        const uint32_t khb = sb + O_KH + buf * TBYTES, klb = sb + O_KL + buf * TBYTES;
        #pragma unroll
        for (int k = 0; k < 4; ++k) {
            uint32_t aq[4], bh[4], bl[4];
            uint32_t kcol = (uint32_t)(k * 16 * 2);
            ldsm4(aq, sb + O_QH + A_off + kcol + (uint32_t)(w * 16 * STR * 2));
            #pragma unroll
            for (int np = 0; np < 4; ++np) {
                uint32_t jo = (uint32_t)(np * 16 * STR * 2);
                ldsm4(bh, khb + B_off + jo + kcol);
                ldsm4(bl, klb + B_off + jo + kcol);
                mma_f16(sc[2 * np],     aq, bh[0], bh[1]);
                mma_f16(sc[2 * np],     aq, bl[0], bl[1]);
                mma_f16(sc[2 * np + 1], aq, bh[2], bh[3]);
                mma_f16(sc[2 * np + 1], aq, bl[2], bl[3]);
            }
        }

        // --- exp + mask + attn store + register repack to fp16 A-frags ---
        uint32_t ah_[4][4];
        const int gjb = ct * 64 + 2 * t;
        #pragma unroll
        for (int nb = 0; nb < 8; ++nb) {
            int gj = gjb + nb * 8;   // global col of this thread's pair
            float p00 = (gj < gi0)     ? __expf(sc[nb][0] - sh0) : 0.f;
            float p01 = (gj + 1 < gi0) ? __expf(sc[nb][1] - sh0) : 0.f;
            float p10 = (gj < gi1)     ? __expf(sc[nb][2] - sh1) : 0.f;
            float p11 = (gj + 1 < gi1) ? __expf(sc[nb][3] - sh1) : 0.f;
            rs0 += p00 + p01;
            rs1 += p10 + p11;
            *(float2*)(arow0 + gj) = make_float2(p00, p01);
            *(float2*)(arow1 + gj) = make_float2(p10, p11);
            int kb = nb >> 1, o = (nb & 1) * 2;
            ah_[kb][o]     = h2u(__floats2half2_rn(p00, p01));
            ah_[kb][o + 1] = h2u(__floats2half2_rn(p10, p11));
        }

        // --- O += P @ V (single fp16 term; A from registers, B via trans LDSM) ---
        const uint32_t vhb = sb + O_VH + buf * TBYTES;
        #pragma unroll
        for (int kb = 0; kb < 4; ++kb) {
            uint32_t jo = (uint32_t)(kb * 16 * STR * 2);
            #pragma unroll
            for (int ep = 0; ep < 4; ++ep) {
                uint32_t vh[4];
                ldsm4t(vh, vhb + Vt_off + jo + (uint32_t)(ep * 16 * 2));
                mma_f16(oc[2 * ep],     ah_[kb], vh[0], vh[1]);
                mma_f16(oc[2 * ep + 1], ah_[kb], vh[2], vh[3]);
            }
        }

        if (ct + 1 < nt) CP_WAIT0();
        __syncthreads();
    }

    // ---- rowsum reduce within the 4-thread column groups ----
    rs0 += __shfl_xor_sync(0xffffffffu, rs0, 1);
    rs0 += __shfl_xor_sync(0xffffffffu, rs0, 2);
    rs1 += __shfl_xor_sync(0xffffffffu, rs1, 1);
    rs1 += __shfl_xor_sync(0xffffffffu, rs1, 2);
    if (t == 0) {
        g_rowsum[bS + gi0] = rs0;
        g_rowsum[bS + gi1] = rs1;
    }

    // ---- out epilogue (normalized in-kernel) ----
    {
        float* o0 = out + (bS + gi0) * ND;
        float* o1 = out + (bS + gi1) * ND;
        if (gi0 == 0) {
            const float* vr = v + bS * ND;  // row 0: softmax over single -50000 diag
            #pragma unroll
            for (int nb = 0; nb < 8; ++nb) {
                int c = nb * 8 + 2 * t;
                *(float2*)(o0 + c) = *(const float2*)(vr + c);
            }
        } else {
            float i0 = 1.0f / rs0;
            #pragma unroll
            for (int nb = 0; nb < 8; ++nb) {
                int c = nb * 8 + 2 * t;
                *(float2*)(o0 + c) = make_float2(oc[nb][0] * i0, oc[nb][1] * i0);
            }
        }
        float i1 = 1.0f / rs1;
        #pragma unroll
        for (int nb = 0; nb < 8; ++nb) {
            int c = nb * 8 + 2 * t;
            *(float2*)(o1 + c) = make_float2(oc[nb][2] * i1, oc[nb][3] * i1);
        }
    }

    // ---- zero-fill upper-triangle columns ----
    {
        int cstart = nt * 64;
        int r = tid >> 1;
        float* rowp = attn_b + (size_t)(rt * 64 + r) * NS;
        float4 z = make_float4(0.f, 0.f, 0.f, 0.f);
        for (int c = cstart + (tid & 1) * 4; c < NS; c += 8)
            *(float4*)(rowp + c) = z;
    }
}

// ---------------------------------------------------------------------------
// Kernel 3: normalize attn rows (lower triangle only), balanced:
// CTA x handles rows x and NS-1-x (pair总 = 4097 elements, constant).
// ---------------------------------------------------------------------------
__global__ void normalize_attn(float* __restrict__ attn) {
    const int x = blockIdx.x, b = blockIdx.y, tid = threadIdx.x;
    float* base = attn + (size_t)b * NS * NS;
    {
        const int i = x;
        float* arow = base + (size_t)i * NS;
        if (i == 0) {
            if (tid == 0) arow[0] = 1.0f;
        } else {
            const float inv = 1.0f / g_rowsum[(size_t)b * NS + i];
            const int n4 = (i >> 2) + 1;
            for (int c4 = tid; c4 < n4; c4 += blockDim.x) {
                float4 a = *(float4*)(arow + c4 * 4);
                a.x *= inv; a.y *= inv; a.z *= inv; a.w *= inv;
                *(float4*)(arow + c4 * 4) = a;
            }
        }
    }
    {
        const int i = NS - 1 - x;
        float* arow = base + (size_t)i * NS;
        const float inv = 1.0f / g_rowsum[(size_t)b * NS + i];
        const int n4 = (i >> 2) + 1;
        for (int c4 = tid; c4 < n4; c4 += blockDim.x) {
            float4 a = *(float4*)(arow + c4 * 4);
            a.x *= inv; a.y *= inv; a.z *= inv; a.w *= inv;
            *(float4*)(arow + c4 * 4) = a;
        }
    }
}

// ---------------------------------------------------------------------------
extern "C" void kernel_launch(void* const* d_in, const int* in_sizes, int n_in,
                              void* d_out, int out_size) {
    const float* qk = (const float*)d_in[0];
    const float* v  = (const float*)d_in[1];
    float* out  = (float*)d_out;
    float* attn = out + (size_t)NB * NS * ND;

    cudaFuncSetAttribute(attn_main, cudaFuncAttributeMaxDynamicSharedMemorySize, SMEM_SZ);
    prep_kernel<<<NB * NS / 8, 256>>>(qk, v);
    attn_main<<<256, 128, SMEM_SZ>>>(v, out, attn);
    normalize_attn<<<dim3(NS / 2, NB), 256>>>(attn);
}